// round 7
// baseline (speedup 1.0000x reference)
#include <cuda_runtime.h>
#include <cuda_fp16.h>
#include <cstdint>

#define NUM_E 8
#define TOK   16384
#define DIN   2048
#define DOUT  2048
#define RNK   64
#define LSCALE 2.0f

// ---------------------------------------------------------------------------
// Scratch (allocation-free device globals) — all fp16, rna-rounded
// ---------------------------------------------------------------------------
__device__ __half xh_g[(size_t)TOK * DIN];                // x
__device__ __half wh_g[(size_t)NUM_E * DIN * DOUT];       // w_base [E][K][N]
__device__ __half wah_g[(size_t)NUM_E * DIN * RNK];       // w_a    [E][K][R]
__device__ __half wbh_g[(size_t)NUM_E * RNK * DOUT];      // w_b    [E][R][N]
__device__ __half gmid_g[(size_t)TOK * RNK];              // SCALE*(x@w_a)

__device__ __forceinline__ int find_expert(const int* __restrict__ tpe, int m0) {
    int e = 0, cum = 0;
#pragma unroll
    for (int i = 0; i < NUM_E; ++i) {
        cum += tpe[i];
        if (m0 >= cum) e++;
    }
    return e;
}

__device__ __forceinline__ uint32_t smem_u32(const void* p) {
    uint32_t a;
    asm("{ .reg .u64 t; cvta.to.shared.u64 t, %1; cvt.u32.u64 %0, t; }"
        : "=r"(a) : "l"(p));
    return a;
}

__device__ __forceinline__ void cp16(uint32_t dst, const void* src) {
    asm volatile("cp.async.cg.shared.global [%0], [%1], 16;" :: "r"(dst), "l"(src));
}
#define CP_COMMIT() asm volatile("cp.async.commit_group;" ::: "memory")
#define CP_WAIT(n)  asm volatile("cp.async.wait_group %0;" :: "n"(n) : "memory")

__device__ __forceinline__ void ldsm4(unsigned& r0, unsigned& r1, unsigned& r2,
                                      unsigned& r3, uint32_t addr) {
    asm volatile("ldmatrix.sync.aligned.m8n8.x4.shared.b16 {%0,%1,%2,%3}, [%4];"
                 : "=r"(r0), "=r"(r1), "=r"(r2), "=r"(r3) : "r"(addr));
}
__device__ __forceinline__ void ldsm4t(unsigned& r0, unsigned& r1, unsigned& r2,
                                       unsigned& r3, uint32_t addr) {
    asm volatile("ldmatrix.sync.aligned.m8n8.x4.trans.shared.b16 {%0,%1,%2,%3}, [%4];"
                 : "=r"(r0), "=r"(r1), "=r"(r2), "=r"(r3) : "r"(addr));
}

__device__ __forceinline__ void mma16(float* c,
                                      unsigned a0, unsigned a1, unsigned a2, unsigned a3,
                                      unsigned b0, unsigned b1) {
    asm volatile(
        "mma.sync.aligned.m16n8k16.row.col.f32.f16.f16.f32 "
        "{%0,%1,%2,%3}, {%4,%5,%6,%7}, {%8,%9}, {%0,%1,%2,%3};"
        : "+f"(c[0]), "+f"(c[1]), "+f"(c[2]), "+f"(c[3])
        : "r"(a0), "r"(a1), "r"(a2), "r"(a3), "r"(b0), "r"(b1));
}

// ---------------------------------------------------------------------------
// Kernel 0: straight fp32 -> fp16 (rna) conversion, 8 elems/thread
// ---------------------------------------------------------------------------
__global__ void __launch_bounds__(256)
conv_half_kernel(const float* __restrict__ src, __half* __restrict__ dst) {
    size_t i = ((size_t)blockIdx.x * 256 + threadIdx.x) * 8;
    float4 v0 = *(const float4*)(src + i);
    float4 v1 = *(const float4*)(src + i + 4);
    __half2 h[4];
    h[0] = __floats2half2_rn(v0.x, v0.y);
    h[1] = __floats2half2_rn(v0.z, v0.w);
    h[2] = __floats2half2_rn(v1.x, v1.y);
    h[3] = __floats2half2_rn(v1.z, v1.w);
    *(uint4*)(dst + i) = *(uint4*)h;
}

// ---------------------------------------------------------------------------
// Kernel 1: gmid = fp16(LSCALE * (xh @ wah[e]))   fp16 mma + ldmatrix
// BM=128, BN=64, BK=32; 4 warps (2m x 2n), warp tile 64x32; 4-stage cp.async.
// ---------------------------------------------------------------------------
#define M_AST 40
#define M_BST 72
#define M_AH  (128 * M_AST)
#define M_BH  (32 * M_BST)
#define M_STAGE (M_AH + M_BH)
#define M_SMEM  (4 * M_STAGE * 2)

__global__ void __launch_bounds__(128, 2)
lora_mid_kernel(const int* __restrict__ tpe)
{
    extern __shared__ __align__(16) __half sm[];
    const uint32_t sbase = smem_u32(sm);

    const int tid = threadIdx.x;
    const int m0 = blockIdx.x * 128;
    const int e = find_expert(tpe, m0);
    const __half* xa = xh_g + (size_t)m0 * DIN;
    const __half* wa = wah_g + (size_t)e * DIN * RNK;

    const int warp = tid >> 5, lane = tid & 31;
    const int wm = warp >> 1, wn = warp & 1;
    const int g = lane >> 2, t = lane & 3;

    const int arow = ((lane >> 3) & 1) * 8 + (lane & 7);
    const int akoff = (lane >> 4) * 8;
    const int bm = lane >> 3;
    const int bkrow = (bm & 1) * 8 + (lane & 7);
    const int bnoff = (bm >> 1) * 8;

    auto load_stage = [&](int kt, int s) {
        const int k0 = kt * 32;
        const uint32_t abase = sbase + (uint32_t)(s * M_STAGE) * 2u;
        const uint32_t bbase = abase + M_AH * 2u;
#pragma unroll
        for (int i = 0; i < 4; ++i) {
            int idx = tid + i * 128;
            int row = idx >> 2, q = (idx & 3) * 8;
            cp16(abase + (uint32_t)(row * M_AST + q) * 2u,
                 xa + (size_t)row * DIN + k0 + q);
        }
#pragma unroll
        for (int i = 0; i < 2; ++i) {
            int idx = tid + i * 128;
            int row = idx >> 3, q = (idx & 7) * 8;
            cp16(bbase + (uint32_t)(row * M_BST + q) * 2u,
                 wa + (size_t)(k0 + row) * RNK + q);
        }
    };

    float acc[4][4][4];
#pragma unroll
    for (int i = 0; i < 4; i++)
#pragma unroll
        for (int j = 0; j < 4; j++)
#pragma unroll
            for (int k = 0; k < 4; k++) acc[i][j][k] = 0.f;

#pragma unroll
    for (int p = 0; p < 3; ++p) { load_stage(p, p); CP_COMMIT(); }

    const int NKTm = DIN / 32;   // 64
#pragma unroll 1
    for (int kt = 0; kt < NKTm; ++kt) {
        CP_WAIT(2);
        __syncthreads();
        const int kp = kt + 3;
        if (kp < NKTm) load_stage(kp, kp & 3);
        CP_COMMIT();

        const uint32_t Ab = sbase + (uint32_t)((kt & 3) * M_STAGE) * 2u;
        const uint32_t Bb = Ab + M_AH * 2u;
        const uint32_t aoff = Ab + (uint32_t)((wm * 64 + arow) * M_AST + akoff) * 2u;
        const uint32_t boff = Bb + (uint32_t)(bkrow * M_BST + wn * 32 + bnoff) * 2u;
#pragma unroll
        for (int ks = 0; ks < 2; ++ks) {
            const int kk = ks * 16;
            unsigned af[4][4], bf[4][2];
#pragma unroll
            for (int mt = 0; mt < 4; ++mt)
                ldsm4(af[mt][0], af[mt][1], af[mt][2], af[mt][3],
                      aoff + (uint32_t)(mt * 16 * M_AST + kk) * 2u);
#pragma unroll
            for (int p = 0; p < 2; ++p)
                ldsm4t(bf[2 * p][0], bf[2 * p][1], bf[2 * p + 1][0], bf[2 * p + 1][1],
                       boff + (uint32_t)(kk * M_BST + p * 16) * 2u);
#pragma unroll
            for (int mt = 0; mt < 4; ++mt)
#pragma unroll
                for (int nt = 0; nt < 4; ++nt)
                    mma16(acc[mt][nt], af[mt][0], af[mt][1], af[mt][2], af[mt][3],
                          bf[nt][0], bf[nt][1]);
        }
    }

#pragma unroll
    for (int mt = 0; mt < 4; ++mt)
#pragma unroll
        for (int nt = 0; nt < 4; ++nt) {
            int r = m0 + wm * 64 + mt * 16 + g;
            int c = wn * 32 + nt * 8 + 2 * t;
            __half2 v0 = __floats2half2_rn(LSCALE * acc[mt][nt][0], LSCALE * acc[mt][nt][1]);
            __half2 v1 = __floats2half2_rn(LSCALE * acc[mt][nt][2], LSCALE * acc[mt][nt][3]);
            *(__half2*)&gmid_g[(size_t)r * RNK + c] = v0;
            *(__half2*)&gmid_g[(size_t)(r + 8) * RNK + c] = v1;
        }
}

// ---------------------------------------------------------------------------
// Kernel 2: main GEMM. out = xh @ wh[e] + gmid @ wbh[e]  (composite K = 2112)
// BM=128 BN=128 BK=64; 4 warps (2x2), warp tile 64x64; ldmatrix + trans;
// 3-stage cp.async; register double-buffered fragments (software pipeline);
// 2 CTAs/SM.
// ---------------------------------------------------------------------------
#define AST 72
#define BST 136
#define A_H (128 * AST)                 // 9216 halves
#define B_H (64 * BST)                  // 8704 halves
#define STAGE_H (A_H + B_H)             // 17920 halves = 35840 B
#define NKT ((DIN + RNK) / 64)          // 33
#define GEMM_SMEM (3 * STAGE_H * 2)     // 107520 B

__global__ void __launch_bounds__(128, 2)
gemm_main(const int* __restrict__ tpe, float* __restrict__ out)
{
    extern __shared__ __align__(16) __half sm[];
    const uint32_t sbase = smem_u32(sm);

    const int tid = threadIdx.x;
    const int m0 = blockIdx.x * 128;   // m fastest: wave shares weight slice via L2
    const int n0 = blockIdx.y * 128;
    const int e = find_expert(tpe, m0);
    const __half* wb  = wh_g  + (size_t)e * DIN * DOUT + n0;
    const __half* wlb = wbh_g + (size_t)e * RNK * DOUT + n0;
    const __half* xa = xh_g + (size_t)m0 * DIN;
    const __half* ga = gmid_g + (size_t)m0 * RNK;

    const int warp = tid >> 5, lane = tid & 31;
    const int wm = warp >> 1, wn = warp & 1;
    const int g = lane >> 2, t = lane & 3;

    const int arow = ((lane >> 3) & 1) * 8 + (lane & 7);
    const int akoff = (lane >> 4) * 8;
    const int bm = lane >> 3;
    const int bkrow = (bm & 1) * 8 + (lane & 7);
    const int bnoff = (bm >> 1) * 8;

    auto load_stage = [&](int kt, int s) {
        const int k0 = kt * 64;
        const bool lora = (k0 >= DIN);
        const uint32_t abase = sbase + (uint32_t)(s * STAGE_H) * 2u;
        const uint32_t bbase = abase + A_H * 2u;
        // A tile: 128 m x 64 k = 8192 halves = 1024 cp16
#pragma unroll
        for (int i = 0; i < 8; ++i) {
            int idx = tid + i * 128;
            int row = idx >> 3, q = (idx & 7) * 8;
            const __half* src = lora ? ga + (size_t)row * RNK + (k0 - DIN) + q
                                     : xa + (size_t)row * DIN + k0 + q;
            cp16(abase + (uint32_t)(row * AST + q) * 2u, src);
        }
        // B tile: 64 k x 128 n = 8192 halves = 1024 cp16
#pragma unroll
        for (int i = 0; i < 8; ++i) {
            int idx = tid + i * 128;
            int row = idx >> 4, q = (idx & 15) * 8;
            const __half* src = lora ? wlb + (size_t)(k0 - DIN + row) * DOUT + q
                                     : wb + (size_t)(k0 + row) * DOUT + q;
            cp16(bbase + (uint32_t)(row * BST + q) * 2u, src);
        }
    };

    // fragment register double buffer
    unsigned af[2][4][4], bf[2][8][2];

    auto load_frags = [&](uint32_t Ab, int kk, int buf) {
        const uint32_t Bb = Ab + A_H * 2u;
        const uint32_t ao = Ab + (uint32_t)((wm * 64 + arow) * AST + akoff + kk) * 2u;
        const uint32_t bo = Bb + (uint32_t)((bkrow + kk) * BST + wn * 64 + bnoff) * 2u;
#pragma unroll
        for (int mt = 0; mt < 4; ++mt)
            ldsm4(af[buf][mt][0], af[buf][mt][1], af[buf][mt][2], af[buf][mt][3],
                  ao + (uint32_t)(mt * 16 * AST) * 2u);
#pragma unroll
        for (int p = 0; p < 4; ++p)
            ldsm4t(bf[buf][2 * p][0], bf[buf][2 * p][1],
                   bf[buf][2 * p + 1][0], bf[buf][2 * p + 1][1],
                   bo + (uint32_t)(p * 16) * 2u);
    };

    float acc[4][8][4];
#pragma unroll
    for (int i = 0; i < 4; i++)
#pragma unroll
        for (int j = 0; j < 8; j++)
#pragma unroll
            for (int k = 0; k < 4; k++) acc[i][j][k] = 0.f;

    // prologue: prefetch 2 stages
    load_stage(0, 0); CP_COMMIT();
    load_stage(1, 1); CP_COMMIT();
    CP_WAIT(1);
    __syncthreads();
    load_frags(sbase, 0, 0);

#pragma unroll 1
    for (int kt = 0; kt < NKT; ++kt) {
        // producer: fill stage kt+2 (its slot is free — consumed at kt-1)
        if (kt + 2 < NKT) load_stage(kt + 2, (kt + 2) % 3);
        CP_COMMIT();

        const uint32_t Ab = sbase + (uint32_t)((kt % 3) * STAGE_H) * 2u;
#pragma unroll
        for (int ks = 0; ks < 4; ++ks) {
            const int cur = ks & 1, nxt = cur ^ 1;
            if (ks < 3) {
                load_frags(Ab, (ks + 1) * 16, nxt);
            } else {
                // stage kt+1 ready after this wait; all warps done reading kt
                CP_WAIT(1);
                __syncthreads();
                if (kt + 1 < NKT) {
                    const uint32_t AbN = sbase + (uint32_t)(((kt + 1) % 3) * STAGE_H) * 2u;
                    load_frags(AbN, 0, nxt);
                }
            }
#pragma unroll
            for (int mt = 0; mt < 4; ++mt)
#pragma unroll
                for (int nt = 0; nt < 8; ++nt)
                    mma16(acc[mt][nt], af[cur][mt][0], af[cur][mt][1],
                          af[cur][mt][2], af[cur][mt][3],
                          bf[cur][nt][0], bf[cur][nt][1]);
        }
    }

#pragma unroll
    for (int mt = 0; mt < 4; ++mt)
#pragma unroll
        for (int nt = 0; nt < 8; ++nt) {
            int r = m0 + wm * 64 + mt * 16 + g;
            int c = n0 + wn * 64 + nt * 8 + 2 * t;
            float2 v0 = {acc[mt][nt][0], acc[mt][nt][1]};
            float2 v1 = {acc[mt][nt][2], acc[mt][nt][3]};
            *(float2*)&out[(size_t)r * DOUT + c] = v0;
            *(float2*)&out[(size_t)(r + 8) * DOUT + c] = v1;
        }
}

// ---------------------------------------------------------------------------
extern "C" void kernel_launch(void* const* d_in, const int* in_sizes, int n_in,
                              void* d_out, int out_size) {
    const float* x      = (const float*)d_in[0];
    const int*   tpe    = (const int*)d_in[1];
    const float* w_base = (const float*)d_in[2];
    const float* w_a    = (const float*)d_in[3];
    const float* w_b    = (const float*)d_in[4];
    float* out = (float*)d_out;
    (void)in_sizes; (void)n_in; (void)out_size;

    __half* xh = nullptr;  cudaGetSymbolAddress((void**)&xh,  xh_g);
    __half* wh = nullptr;  cudaGetSymbolAddress((void**)&wh,  wh_g);
    __half* wah = nullptr; cudaGetSymbolAddress((void**)&wah, wah_g);
    __half* wbh = nullptr; cudaGetSymbolAddress((void**)&wbh, wbh_g);

    // 0) fp32 -> fp16 conversions (no transposes)
    conv_half_kernel<<<(TOK * DIN) / 2048, 256>>>(x, xh);
    conv_half_kernel<<<((size_t)NUM_E * DIN * DOUT) / 2048, 256>>>(w_base, wh);
    conv_half_kernel<<<((size_t)NUM_E * DIN * RNK) / 2048, 256>>>(w_a, wah);
    conv_half_kernel<<<((size_t)NUM_E * RNK * DOUT) / 2048, 256>>>(w_b, wbh);

    // 1) LoRA mid
    cudaFuncSetAttribute(lora_mid_kernel, cudaFuncAttributeMaxDynamicSharedMemorySize, M_SMEM);
    lora_mid_kernel<<<TOK / 128, 128, M_SMEM>>>(tpe);

    // 2) main GEMM (composite K = 2112, BK=64)
    cudaFuncSetAttribute(gemm_main, cudaFuncAttributeMaxDynamicSharedMemorySize, GEMM_SMEM);
    gemm_main<<<dim3(TOK / 128, DOUT / 128), 128, GEMM_SMEM>>>(tpe, out);
}